// round 8
// baseline (speedup 1.0000x reference)
#include <cuda_runtime.h>
#include <math.h>
#include <stdint.h>

#define NB 20000
#define NA 80000
#define NE 320000
#define NC 128
#define NG 512
#define PI_F 3.14159265358979323846f

// ---------------- scratch (device globals; no allocation allowed) -------------
__device__ float g_Zb[NB * 3];
__device__ float g_cnt[NB];
__device__ float g_hs[NB * NC];            // h_s [n][c]
__device__ float g_hv[NB * 3 * NC];        // h_v [n][x][c]
__device__ float g_aggs[NB * NC];          // agg_s [n][c]
__device__ float g_aggv[NB * 3 * NC];      // agg_v [n][x][c]
__device__ float g_rfeat[NE * 16];
__device__ float g_u[NE * 3];

// ---------------- helpers ----------------------------------------------------
__device__ __forceinline__ void red_add_v4(float* addr, float4 v) {
    asm volatile("red.global.add.v4.f32 [%0], {%1,%2,%3,%4};"
                 :: "l"(addr), "f"(v.x), "f"(v.y), "f"(v.z), "f"(v.w)
                 : "memory");
}
__device__ __forceinline__ float4 f4fma(float a, float4 b, float4 c) {
    c.x += a * b.x; c.y += a * b.y; c.z += a * b.z; c.w += a * b.w; return c;
}
__device__ __forceinline__ float4 f4add(float4 a, float4 b) {
    a.x += b.x; a.y += b.y; a.z += b.z; a.w += b.w; return a;
}
__device__ __forceinline__ float4 f4scale(float4 a, float s) {
    a.x *= s; a.y *= s; a.z *= s; a.w *= s; return a;
}
// packed f32x2 (Blackwell FFMA2 — PTX-only path)
__device__ __forceinline__ unsigned long long pk2(float lo, float hi) {
    unsigned long long r;
    asm("mov.b64 %0, {%1, %2};" : "=l"(r) : "f"(lo), "f"(hi));
    return r;
}
__device__ __forceinline__ unsigned long long fma2(unsigned long long a,
                                                   unsigned long long b,
                                                   unsigned long long c) {
    unsigned long long d;
    asm("fma.rn.f32x2 %0, %1, %2, %3;" : "=l"(d) : "l"(a), "l"(b), "l"(c));
    return d;
}
__device__ __forceinline__ float up2sum(unsigned long long v) {
    float lo, hi;
    asm("mov.b64 {%0, %1}, %2;" : "=f"(lo), "=f"(hi) : "l"(v));
    return lo + hi;
}

// ---------------- 1. atom -> block scatter (sums) -----------------------------
__global__ void atom_scatter(const float* __restrict__ H, const float* __restrict__ Z,
                             const int* __restrict__ bid, float* __restrict__ HbSum) {
    int t = blockIdx.x * blockDim.x + threadIdx.x;
    int a = t >> 5;
    if (a >= NA) return;
    int lane = t & 31;
    int b = bid[a];
    float4 v = *(const float4*)(H + (size_t)a * NC + lane * 4);
    red_add_v4(HbSum + (size_t)b * NC + lane * 4, v);
    if (lane < 3) atomicAdd(&g_Zb[b * 3 + lane], Z[a * 3 + lane]);
    if (lane == 0) atomicAdd(&g_cnt[b], 1.0f);
}

// ---------------- 2. finalize means ------------------------------------------
__global__ void finalize_blocks(float* __restrict__ Hb) {
    int t = blockIdx.x * blockDim.x + threadIdx.x;
    int b = t >> 5;
    if (b >= NB) return;
    int lane = t & 31;
    float inv = 1.0f / fmaxf(g_cnt[b], 1.0f);
    float4* p = (float4*)(Hb + (size_t)b * NC + lane * 4);
    *p = f4scale(*p, inv);
    if (lane < 3) g_Zb[b * 3 + lane] *= inv;
}

// ---------------- 3. edge geometry: u, r_feat --------------------------------
__global__ void edge_geom(const int* __restrict__ edges) {
    int e = blockIdx.x * blockDim.x + threadIdx.x;
    if (e >= NE) return;
    int s = edges[e], d_ = edges[NE + e];
    float rx = g_Zb[d_ * 3 + 0] - g_Zb[s * 3 + 0];
    float ry = g_Zb[d_ * 3 + 1] - g_Zb[s * 3 + 1];
    float rz = g_Zb[d_ * 3 + 2] - g_Zb[s * 3 + 2];
    float d = sqrtf(rx * rx + ry * ry + rz * rz + 1e-12f);
    float invd = 1.0f / d;
    g_u[e * 3 + 0] = rx * invd;
    g_u[e * 3 + 1] = ry * invd;
    g_u[e * 3 + 2] = rz * invd;
    float x = d * 0.2f;  // d / R_MAX
    float fcut = 0.0f;
    if (x < 1.0f) {
        float x2 = x * x, x4 = x2 * x2, x5 = x4 * x;
        fcut = 1.0f - 21.0f * x5 + 35.0f * x5 * x - 15.0f * x5 * x2;
    }
    float pref = 0.6324555320336759f * invd * fcut;  // sqrt(2/5) / d * fcut
    float th = PI_F * 0.2f * d;
    float s1, c1;
    sincosf(th, &s1, &c1);
    float two_c = 2.0f * c1;
    float sk = s1, skm1 = 0.0f;
    float* out = g_rfeat + (size_t)e * 16;
    #pragma unroll
    for (int k = 1; k <= 16; k++) {
        out[k - 1] = pref * sk;
        float nxt = two_c * sk - skm1;
        skm1 = sk; sk = nxt;
    }
}

// ---------------- 4. embed GEMM: h_s = Hb @ W_embed --------------------------
__global__ void __launch_bounds__(256) gemm_embed(const float* __restrict__ A,
                                                  const float* __restrict__ B) {
    extern __shared__ float sm[];
    float* Bs = sm;            // 128*128
    float* As = sm + 16384;    // 64*132
    int tid = threadIdx.x;
    for (int i = tid; i < 16384; i += 256) Bs[i] = B[i];
    int m0 = blockIdx.x * 64;
    for (int i = tid; i < 64 * 32; i += 256) {
        int r = i >> 5, kq = (i & 31) * 4;
        float4 v = make_float4(0, 0, 0, 0);
        int m = m0 + r;
        if (m < NB) v = *(const float4*)(A + (size_t)m * NC + kq);
        *(float4*)(As + r * 132 + kq) = v;
    }
    __syncthreads();
    int tr = (tid >> 4) << 2;
    int tc = (tid & 15) << 3;
    float4 acc0[4] = {}, acc1[4] = {};
    for (int k = 0; k < 128; k++) {
        float4 b0 = *(const float4*)(Bs + k * 128 + tc);
        float4 b1 = *(const float4*)(Bs + k * 128 + tc + 4);
        #pragma unroll
        for (int i = 0; i < 4; i++) {
            float a = As[(tr + i) * 132 + k];
            acc0[i] = f4fma(a, b0, acc0[i]);
            acc1[i] = f4fma(a, b1, acc1[i]);
        }
    }
    #pragma unroll
    for (int i = 0; i < 4; i++) {
        int m = m0 + tr + i;
        if (m >= NB) continue;
        *(float4*)(g_hs + (size_t)m * NC + tc) = acc0[i];
        *(float4*)(g_hs + (size_t)m * NC + tc + 4) = acc1[i];
    }
}

// ---------------- 5. edge message kernel (4 edges/warp, FFMA2 packed) ---------
// Phase A: hidden for 4 edges -> SMEM transposed hidT[h][j].
// Phase B: h processed in even/odd pairs via fma.rn.f32x2; Wr2 staged in SMEM
//          pair-interleaved so weight pairs load directly as u64.
// Phase C: gather/scatter per edge (unchanged math).
#define EPW 4  // edges per warp
__global__ void __launch_bounds__(256, 2) edge_msg(const int* __restrict__ edges,
                                                   const float* __restrict__ Wr1,
                                                   const float* __restrict__ br1,
                                                   const float* __restrict__ Wr2) {
    extern __shared__ float sm[];
    float* Wr1s = sm;                  // 16*64
    float* br1s = Wr1s + 16 * 64;      // 64
    float* Wr2p = br1s + 64;           // 64*256 pair-interleaved
    float* hids = Wr2p + 64 * 256;     // nwarps * 64 * EPW
    int tid = threadIdx.x;
    for (int i = tid; i < 16 * 64; i += blockDim.x) Wr1s[i] = Wr1[i];
    for (int i = tid; i < 64; i += blockDim.x) br1s[i] = br1[i];
    // interleave: Wr2p[h2*512 + c*2 + (h&1)] = Wr2[h][c]
    for (int i = tid; i < 64 * 256; i += blockDim.x) {
        int h = i >> 8, c = i & 255;
        Wr2p[(h >> 1) * 512 + c * 2 + (h & 1)] = Wr2[i];
    }
    __syncthreads();

    int warp = tid >> 5, lane = tid & 31;
    int nwarps = blockDim.x >> 5;
    float* hid = hids + warp * (64 * EPW);
    int gw = blockIdx.x * nwarps + warp;
    int wstride = gridDim.x * nwarps;
    int ntiles = NE / EPW;  // 80000, exact

    for (int tile = gw; tile < ntiles; tile += wstride) {
        int e0 = tile * EPW;
        // ---- Phase A: hidden = silu(r_feat @ Wr1 + br1), transposed store ----
        #pragma unroll
        for (int j = 0; j < EPW; j++) {
            int e = e0 + j;
            float rv = (lane < 16) ? g_rfeat[(size_t)e * 16 + lane] : 0.0f;
            float h0 = br1s[lane], h1 = br1s[lane + 32];
            #pragma unroll
            for (int k = 0; k < 16; k++) {
                float r = __shfl_sync(0xffffffffu, rv, k);
                h0 += r * Wr1s[k * 64 + lane];
                h1 += r * Wr1s[k * 64 + lane + 32];
            }
            h0 = h0 / (1.0f + __expf(-h0));
            h1 = h1 / (1.0f + __expf(-h1));
            hid[lane * EPW + j] = h0;
            hid[(lane + 32) * EPW + j] = h1;
        }
        __syncwarp();
        // ---- Phase B: packed even/odd-h FMA2 accumulation ----
        int c0 = lane * 4;
        unsigned long long aws[EPW][4], awv[EPW][4];
        #pragma unroll
        for (int j = 0; j < EPW; j++)
            #pragma unroll
            for (int c = 0; c < 4; c++) { aws[j][c] = 0ull; awv[j][c] = 0ull; }
        #pragma unroll 4
        for (int h2 = 0; h2 < 32; h2++) {
            float4 rA = *(const float4*)(hid + (2 * h2) * EPW);
            float4 rB = *(const float4*)(hid + (2 * h2 + 1) * EPW);
            unsigned long long hp0 = pk2(rA.x, rB.x);
            unsigned long long hp1 = pk2(rA.y, rB.y);
            unsigned long long hp2 = pk2(rA.z, rB.z);
            unsigned long long hp3 = pk2(rA.w, rB.w);
            unsigned long long hp[EPW] = {hp0, hp1, hp2, hp3};
            const float* base = Wr2p + h2 * 512;
            ulonglong2 wa0 = *(const ulonglong2*)(base + c0 * 2);
            ulonglong2 wa1 = *(const ulonglong2*)(base + c0 * 2 + 4);
            ulonglong2 wb0 = *(const ulonglong2*)(base + 256 + c0 * 2);
            ulonglong2 wb1 = *(const ulonglong2*)(base + 256 + c0 * 2 + 4);
            #pragma unroll
            for (int j = 0; j < EPW; j++) {
                aws[j][0] = fma2(hp[j], wa0.x, aws[j][0]);
                aws[j][1] = fma2(hp[j], wa0.y, aws[j][1]);
                aws[j][2] = fma2(hp[j], wa1.x, aws[j][2]);
                aws[j][3] = fma2(hp[j], wa1.y, aws[j][3]);
                awv[j][0] = fma2(hp[j], wb0.x, awv[j][0]);
                awv[j][1] = fma2(hp[j], wb0.y, awv[j][1]);
                awv[j][2] = fma2(hp[j], wb1.x, awv[j][2]);
                awv[j][3] = fma2(hp[j], wb1.y, awv[j][3]);
            }
        }
        // ---- Phase C: hoisted index/u loads, then gather + scatter ----
        int sidx[EPW], didx[EPW];
        float ux[EPW], uy[EPW], uz[EPW];
        #pragma unroll
        for (int j = 0; j < EPW; j++) {
            int e = e0 + j;
            sidx[j] = edges[e];
            didx[j] = edges[NE + e];
            ux[j] = g_u[e * 3 + 0];
            uy[j] = g_u[e * 3 + 1];
            uz[j] = g_u[e * 3 + 2];
        }
        #pragma unroll
        for (int j = 0; j < EPW; j++) {
            int s = sidx[j], dst = didx[j];
            if (s == dst) continue;  // mask==0
            float4 ws = make_float4(up2sum(aws[j][0]), up2sum(aws[j][1]),
                                    up2sum(aws[j][2]), up2sum(aws[j][3]));
            float4 wv = make_float4(up2sum(awv[j][0]), up2sum(awv[j][1]),
                                    up2sum(awv[j][2]), up2sum(awv[j][3]));
            float4 hs = *(const float4*)(g_hs + (size_t)s * NC + c0);
            float4 ms = make_float4(ws.x * hs.x, ws.y * hs.y,
                                    ws.z * hs.z, ws.w * hs.w);
            red_add_v4(g_aggs + (size_t)dst * NC + c0, ms);
            const float* hvp = g_hv + (size_t)s * 384;
            float* avp = g_aggv + (size_t)dst * 384;
            float u3[3] = {ux[j], uy[j], uz[j]};
            #pragma unroll
            for (int x = 0; x < 3; x++) {
                float4 hv4 = *(const float4*)(hvp + x * NC + c0);
                float u = u3[x];
                float4 mv;
                mv.x = wv.x * (hv4.x + hs.x * u);
                mv.y = wv.y * (hv4.y + hs.y * u);
                mv.z = wv.z * (hv4.z + hs.z * u);
                mv.w = wv.w * (hv4.w + hs.w * u);
                red_add_v4(avp + x * NC + c0, mv);
            }
        }
    }
}

// ---------------- 6. node s-update GEMM --------------------------------------
// s_out = a@W0 + a^2@W1 + a^3@W2 ; h_s update + feats write
// W0/W1 staged in SMEM; W2 streamed through read-only cache (fits L1/L2,
// reused by every CTA) to keep SMEM under the 227 KB sm_100a limit.
__global__ void __launch_bounds__(256) gemm_s(const float* __restrict__ Wsl, int l,
                                              float* __restrict__ outB) {
    extern __shared__ float sm[];
    float* W0 = sm;
    float* W1 = sm + 16384;
    float* As = sm + 32768;  // 64*132
    const float* W2 = Wsl + 32768;
    int tid = threadIdx.x;
    for (int i = tid; i < 2 * 16384; i += 256) sm[i] = Wsl[i];
    int m0 = blockIdx.x * 64;
    for (int i = tid; i < 64 * 32; i += 256) {
        int r = i >> 5, kq = (i & 31) * 4;
        float4 v = make_float4(0, 0, 0, 0);
        int m = m0 + r;
        if (m < NB) v = *(const float4*)(g_aggs + (size_t)m * NC + kq);
        *(float4*)(As + r * 132 + kq) = v;
    }
    __syncthreads();
    int tr = (tid >> 4) << 2;
    int tc = (tid & 15) << 3;
    float4 acc0[4] = {}, acc1[4] = {};
    for (int k = 0; k < 128; k++) {
        float4 b00 = *(const float4*)(W0 + k * 128 + tc);
        float4 b01 = *(const float4*)(W0 + k * 128 + tc + 4);
        float4 b10 = *(const float4*)(W1 + k * 128 + tc);
        float4 b11 = *(const float4*)(W1 + k * 128 + tc + 4);
        float4 b20 = __ldg((const float4*)(W2 + k * 128 + tc));
        float4 b21 = __ldg((const float4*)(W2 + k * 128 + tc + 4));
        #pragma unroll
        for (int i = 0; i < 4; i++) {
            float a = As[(tr + i) * 132 + k];
            float a2 = a * a, a3 = a2 * a;
            acc0[i] = f4fma(a, b00, acc0[i]);
            acc0[i] = f4fma(a2, b10, acc0[i]);
            acc0[i] = f4fma(a3, b20, acc0[i]);
            acc1[i] = f4fma(a, b01, acc1[i]);
            acc1[i] = f4fma(a2, b11, acc1[i]);
            acc1[i] = f4fma(a3, b21, acc1[i]);
        }
    }
    #pragma unroll
    for (int i = 0; i < 4; i++) {
        int m = m0 + tr + i;
        if (m >= NB) continue;
        float* hsrow = g_hs + (size_t)m * NC + tc;
        float4 v0 = acc0[i], v1 = acc1[i];
        if (l) {
            v0 = f4add(v0, *(float4*)hsrow);
            v1 = f4add(v1, *(float4*)(hsrow + 4));
        }
        *(float4*)hsrow = v0;
        *(float4*)(hsrow + 4) = v1;
        float* fo = outB + (size_t)m * 1024 + l * 512 + tc;
        *(float4*)fo = v0;
        *(float4*)(fo + 4) = v1;
    }
}

// ---------------- 7. node v-update GEMM --------------------------------------
// rows are (n,x): v_out = agg_v @ Wv + wsv*agg_s*agg_v ; h_v update + feats write
__global__ void __launch_bounds__(256) gemm_v(const float* __restrict__ Wvl,
                                              const float* __restrict__ wsvl, int l,
                                              float* __restrict__ outB) {
    extern __shared__ float sm[];
    float* Bs = sm;            // 128*128
    float* As = sm + 16384;    // 64*132
    __shared__ float wsvs[128];
    int tid = threadIdx.x;
    for (int i = tid; i < 16384; i += 256) Bs[i] = Wvl[i];
    if (tid < 128) wsvs[tid] = wsvl[tid];
    int m0 = blockIdx.x * 64;
    for (int i = tid; i < 64 * 32; i += 256) {
        int r = i >> 5, kq = (i & 31) * 4;
        float4 v = make_float4(0, 0, 0, 0);
        int m = m0 + r;
        if (m < NB * 3) v = *(const float4*)(g_aggv + (size_t)m * NC + kq);
        *(float4*)(As + r * 132 + kq) = v;
    }
    __syncthreads();
    int tr = (tid >> 4) << 2;
    int tc = (tid & 15) << 3;
    float4 acc0[4] = {}, acc1[4] = {};
    for (int k = 0; k < 128; k++) {
        float4 b0 = *(const float4*)(Bs + k * 128 + tc);
        float4 b1 = *(const float4*)(Bs + k * 128 + tc + 4);
        #pragma unroll
        for (int i = 0; i < 4; i++) {
            float a = As[(tr + i) * 132 + k];
            acc0[i] = f4fma(a, b0, acc0[i]);
            acc1[i] = f4fma(a, b1, acc1[i]);
        }
    }
    #pragma unroll
    for (int i = 0; i < 4; i++) {
        int m = m0 + tr + i;
        if (m >= NB * 3) continue;
        int n = m / 3;
        int x = m - 3 * n;
        float4 av0 = *(float4*)(As + (tr + i) * 132 + tc);
        float4 av1 = *(float4*)(As + (tr + i) * 132 + tc + 4);
        float4 as0 = *(const float4*)(g_aggs + (size_t)n * NC + tc);
        float4 as1 = *(const float4*)(g_aggs + (size_t)n * NC + tc + 4);
        float4 sv0 = *(const float4*)(wsvs + tc);
        float4 sv1 = *(const float4*)(wsvs + tc + 4);
        float4 r0 = acc0[i], r1 = acc1[i];
        r0.x += sv0.x * as0.x * av0.x; r0.y += sv0.y * as0.y * av0.y;
        r0.z += sv0.z * as0.z * av0.z; r0.w += sv0.w * as0.w * av0.w;
        r1.x += sv1.x * as1.x * av1.x; r1.y += sv1.y * as1.y * av1.y;
        r1.z += sv1.z * as1.z * av1.z; r1.w += sv1.w * as1.w * av1.w;
        float* hvrow = g_hv + (size_t)m * NC + tc;
        if (l) {
            r0 = f4add(r0, *(float4*)hvrow);
            r1 = f4add(r1, *(float4*)(hvrow + 4));
        }
        *(float4*)hvrow = r0;
        *(float4*)(hvrow + 4) = r1;
        // feats layout: 128 + c*3 + x
        float* fo = outB + (size_t)n * 1024 + l * 512 + 128 + x;
        fo[(tc + 0) * 3] = r0.x; fo[(tc + 1) * 3] = r0.y;
        fo[(tc + 2) * 3] = r0.z; fo[(tc + 3) * 3] = r0.w;
        fo[(tc + 4) * 3] = r1.x; fo[(tc + 5) * 3] = r1.y;
        fo[(tc + 6) * 3] = r1.z; fo[(tc + 7) * 3] = r1.w;
    }
}

// ---------------- 8. normalize rows + scatter to graphs ----------------------
__global__ void norm_block(float* __restrict__ outB, float* __restrict__ outC,
                           const int* __restrict__ batch_id) {
    int t = blockIdx.x * blockDim.x + threadIdx.x;
    int n = t >> 5;
    if (n >= NB) return;
    int lane = t & 31;
    float* row = outB + (size_t)n * 1024;
    float4 v[8];
    float ss = 0.0f;
    #pragma unroll
    for (int i = 0; i < 8; i++) {
        v[i] = *(float4*)(row + i * 128 + lane * 4);
        ss += v[i].x * v[i].x + v[i].y * v[i].y + v[i].z * v[i].z + v[i].w * v[i].w;
    }
    #pragma unroll
    for (int o = 16; o; o >>= 1) ss += __shfl_xor_sync(0xffffffffu, ss, o);
    float inv = 1.0f / fmaxf(sqrtf(ss), 1e-12f);
    int b = batch_id[n];
    float* grow = outC + (size_t)b * 1024;
    #pragma unroll
    for (int i = 0; i < 8; i++) {
        v[i] = f4scale(v[i], inv);
        *(float4*)(row + i * 128 + lane * 4) = v[i];
        red_add_v4(grow + i * 128 + lane * 4, v[i]);
    }
}

__global__ void norm_g(float* __restrict__ outC) {
    int t = blockIdx.x * blockDim.x + threadIdx.x;
    int n = t >> 5;
    if (n >= NG) return;
    int lane = t & 31;
    float* row = outC + (size_t)n * 1024;
    float4 v[8];
    float ss = 0.0f;
    #pragma unroll
    for (int i = 0; i < 8; i++) {
        v[i] = *(float4*)(row + i * 128 + lane * 4);
        ss += v[i].x * v[i].x + v[i].y * v[i].y + v[i].z * v[i].z + v[i].w * v[i].w;
    }
    #pragma unroll
    for (int o = 16; o; o >>= 1) ss += __shfl_xor_sync(0xffffffffu, ss, o);
    float inv = 1.0f / fmaxf(sqrtf(ss), 1e-12f);
    #pragma unroll
    for (int i = 0; i < 8; i++)
        *(float4*)(row + i * 128 + lane * 4) = f4scale(v[i], inv);
}

// ---------------- launch ------------------------------------------------------
extern "C" void kernel_launch(void* const* d_in, const int* in_sizes, int n_in,
                              void* d_out, int out_size) {
    const float* H       = (const float*)d_in[0];
    const float* Z       = (const float*)d_in[1];
    const float* W_embed = (const float*)d_in[2];
    const float* Wr1     = (const float*)d_in[3];
    const float* br1     = (const float*)d_in[4];
    const float* Wr2     = (const float*)d_in[5];
    const float* Ws      = (const float*)d_in[6];
    const float* Wv      = (const float*)d_in[7];
    const float* wsv     = (const float*)d_in[8];
    const int* block_id  = (const int*)d_in[9];
    const int* batch_id  = (const int*)d_in[10];
    const int* edges     = (const int*)d_in[11];

    float* outA = (float*)d_out;                    // Hb        [20000,128]
    float* outB = outA + (size_t)NB * NC;           // block_repr[20000,1024]
    float* outC = outB + (size_t)NB * 1024;         // graph_repr[512,1024]

    const int EM_SMEM = (16 * 64 + 64 + 64 * 256 + 8 * 64 * EPW) * 4;  // 78080
    const int GS_SMEM = (2 * 16384 + 64 * 132) * 4;                 // 164864
    const int GV_SMEM = (16384 + 64 * 132) * 4;                     // 99328

    cudaFuncSetAttribute(edge_msg,   cudaFuncAttributeMaxDynamicSharedMemorySize, EM_SMEM);
    cudaFuncSetAttribute(gemm_s,     cudaFuncAttributeMaxDynamicSharedMemorySize, GS_SMEM);
    cudaFuncSetAttribute(gemm_v,     cudaFuncAttributeMaxDynamicSharedMemorySize, GV_SMEM);
    cudaFuncSetAttribute(gemm_embed, cudaFuncAttributeMaxDynamicSharedMemorySize, GV_SMEM);

    void *pZb, *pcnt, *phv, *paggs, *paggv;
    cudaGetSymbolAddress(&pZb, g_Zb);
    cudaGetSymbolAddress(&pcnt, g_cnt);
    cudaGetSymbolAddress(&phv, g_hv);
    cudaGetSymbolAddress(&paggs, g_aggs);
    cudaGetSymbolAddress(&paggv, g_aggv);

    cudaMemsetAsync(outA, 0, (size_t)NB * NC * 4);
    cudaMemsetAsync(outC, 0, (size_t)NG * 1024 * 4);
    cudaMemsetAsync(pZb, 0, (size_t)NB * 3 * 4);
    cudaMemsetAsync(pcnt, 0, (size_t)NB * 4);
    cudaMemsetAsync(phv, 0, (size_t)NB * 384 * 4);

    atom_scatter<<<(NA * 32 + 255) / 256, 256>>>(H, Z, block_id, outA);
    finalize_blocks<<<(NB * 32 + 255) / 256, 256>>>(outA);
    gemm_embed<<<(NB + 63) / 64, 256, GV_SMEM>>>(outA, W_embed);
    edge_geom<<<(NE + 255) / 256, 256>>>(edges);

    for (int l = 0; l < 2; l++) {
        cudaMemsetAsync(paggs, 0, (size_t)NB * NC * 4);
        cudaMemsetAsync(paggv, 0, (size_t)NB * 384 * 4);
        edge_msg<<<296, 256, EM_SMEM>>>(edges, Wr1 + l * 16 * 64, br1 + l * 64,
                                        Wr2 + l * 64 * 256);
        gemm_s<<<(NB + 63) / 64, 256, GS_SMEM>>>(Ws + (size_t)l * 3 * 16384, l, outB);
        gemm_v<<<(NB * 3 + 63) / 64, 256, GV_SMEM>>>(Wv + (size_t)l * 16384,
                                                     wsv + l * 128, l, outB);
    }

    norm_block<<<(NB * 32 + 255) / 256, 256>>>(outB, outC, batch_id);
    norm_g<<<(NG * 32 + 255) / 256, 256>>>(outC);
}

// round 9
// speedup vs baseline: 1.2193x; 1.2193x over previous
#include <cuda_runtime.h>
#include <math.h>
#include <stdint.h>

#define NB 20000
#define NA 80000
#define NE 320000
#define NC 128
#define NG 512
#define PI_F 3.14159265358979323846f

// ---------------- scratch (device globals; no allocation allowed) -------------
__device__ float g_Zb[NB * 3];
__device__ float g_cnt[NB];
__device__ float g_hs[NB * NC];            // h_s [n][c]
__device__ float g_hv[NB * 3 * NC];        // h_v [n][x][c]
__device__ float g_aggs[NB * NC];          // agg_s [n][c]
__device__ float g_aggv[NB * 3 * NC];      // agg_v [n][x][c]
__device__ float g_rfeat[NE * 16];
__device__ float g_u[NE * 3];

// ---------------- helpers ----------------------------------------------------
__device__ __forceinline__ void red_add_v4(float* addr, float4 v) {
    asm volatile("red.global.add.v4.f32 [%0], {%1,%2,%3,%4};"
                 :: "l"(addr), "f"(v.x), "f"(v.y), "f"(v.z), "f"(v.w)
                 : "memory");
}
__device__ __forceinline__ float4 f4fma(float a, float4 b, float4 c) {
    c.x += a * b.x; c.y += a * b.y; c.z += a * b.z; c.w += a * b.w; return c;
}
__device__ __forceinline__ float4 f4add(float4 a, float4 b) {
    a.x += b.x; a.y += b.y; a.z += b.z; a.w += b.w; return a;
}
__device__ __forceinline__ float4 f4scale(float4 a, float s) {
    a.x *= s; a.y *= s; a.z *= s; a.w *= s; return a;
}

// ---------------- 1. atom -> block scatter (sums) -----------------------------
__global__ void atom_scatter(const float* __restrict__ H, const float* __restrict__ Z,
                             const int* __restrict__ bid, float* __restrict__ HbSum) {
    int t = blockIdx.x * blockDim.x + threadIdx.x;
    int a = t >> 5;
    if (a >= NA) return;
    int lane = t & 31;
    int b = bid[a];
    float4 v = *(const float4*)(H + (size_t)a * NC + lane * 4);
    red_add_v4(HbSum + (size_t)b * NC + lane * 4, v);
    if (lane < 3) atomicAdd(&g_Zb[b * 3 + lane], Z[a * 3 + lane]);
    if (lane == 0) atomicAdd(&g_cnt[b], 1.0f);
}

// ---------------- 2. finalize means ------------------------------------------
__global__ void finalize_blocks(float* __restrict__ Hb) {
    int t = blockIdx.x * blockDim.x + threadIdx.x;
    int b = t >> 5;
    if (b >= NB) return;
    int lane = t & 31;
    float inv = 1.0f / fmaxf(g_cnt[b], 1.0f);
    float4* p = (float4*)(Hb + (size_t)b * NC + lane * 4);
    *p = f4scale(*p, inv);
    if (lane < 3) g_Zb[b * 3 + lane] *= inv;
}

// ---------------- 3. edge geometry: u, r_feat --------------------------------
__global__ void edge_geom(const int* __restrict__ edges) {
    int e = blockIdx.x * blockDim.x + threadIdx.x;
    if (e >= NE) return;
    int s = edges[e], d_ = edges[NE + e];
    float rx = g_Zb[d_ * 3 + 0] - g_Zb[s * 3 + 0];
    float ry = g_Zb[d_ * 3 + 1] - g_Zb[s * 3 + 1];
    float rz = g_Zb[d_ * 3 + 2] - g_Zb[s * 3 + 2];
    float d = sqrtf(rx * rx + ry * ry + rz * rz + 1e-12f);
    float invd = 1.0f / d;
    g_u[e * 3 + 0] = rx * invd;
    g_u[e * 3 + 1] = ry * invd;
    g_u[e * 3 + 2] = rz * invd;
    float x = d * 0.2f;  // d / R_MAX
    float fcut = 0.0f;
    if (x < 1.0f) {
        float x2 = x * x, x4 = x2 * x2, x5 = x4 * x;
        fcut = 1.0f - 21.0f * x5 + 35.0f * x5 * x - 15.0f * x5 * x2;
    }
    float pref = 0.6324555320336759f * invd * fcut;  // sqrt(2/5) / d * fcut
    float th = PI_F * 0.2f * d;
    float s1, c1;
    sincosf(th, &s1, &c1);
    float two_c = 2.0f * c1;
    float sk = s1, skm1 = 0.0f;
    float* out = g_rfeat + (size_t)e * 16;
    #pragma unroll
    for (int k = 1; k <= 16; k++) {
        out[k - 1] = pref * sk;
        float nxt = two_c * sk - skm1;
        skm1 = sk; sk = nxt;
    }
}

// ---------------- 4. embed GEMM: h_s = Hb @ W_embed --------------------------
__global__ void __launch_bounds__(256) gemm_embed(const float* __restrict__ A,
                                                  const float* __restrict__ B) {
    extern __shared__ float sm[];
    float* Bs = sm;            // 128*128
    float* As = sm + 16384;    // 64*132
    int tid = threadIdx.x;
    for (int i = tid; i < 16384; i += 256) Bs[i] = B[i];
    int m0 = blockIdx.x * 64;
    for (int i = tid; i < 64 * 32; i += 256) {
        int r = i >> 5, kq = (i & 31) * 4;
        float4 v = make_float4(0, 0, 0, 0);
        int m = m0 + r;
        if (m < NB) v = *(const float4*)(A + (size_t)m * NC + kq);
        *(float4*)(As + r * 132 + kq) = v;
    }
    __syncthreads();
    int tr = (tid >> 4) << 2;
    int tc = (tid & 15) << 3;
    float4 acc0[4] = {}, acc1[4] = {};
    for (int k = 0; k < 128; k++) {
        float4 b0 = *(const float4*)(Bs + k * 128 + tc);
        float4 b1 = *(const float4*)(Bs + k * 128 + tc + 4);
        #pragma unroll
        for (int i = 0; i < 4; i++) {
            float a = As[(tr + i) * 132 + k];
            acc0[i] = f4fma(a, b0, acc0[i]);
            acc1[i] = f4fma(a, b1, acc1[i]);
        }
    }
    #pragma unroll
    for (int i = 0; i < 4; i++) {
        int m = m0 + tr + i;
        if (m >= NB) continue;
        *(float4*)(g_hs + (size_t)m * NC + tc) = acc0[i];
        *(float4*)(g_hs + (size_t)m * NC + tc + 4) = acc1[i];
    }
}

// ---------------- 5. edge message kernel (8 edges / warp) ---------------------
// Phase A: hidden for 8 edges -> SMEM. Phase B: one pass over Wr2 rows applied
// to all 8 edges. Phase C: gather/scatter per edge.
// __launch_bounds__(256,2): cap at 128 regs so 2 CTAs/SM are resident
// (4 warps/SMSP) to hide Phase-C gather/RED latency. u-loads not hoisted to
// stay under the register cap.
#define EPW 8  // edges per warp
__global__ void __launch_bounds__(256, 2) edge_msg(const int* __restrict__ edges,
                                                   const float* __restrict__ Wr1,
                                                   const float* __restrict__ br1,
                                                   const float* __restrict__ Wr2) {
    extern __shared__ float sm[];
    float* Wr1s = sm;                  // 16*64
    float* br1s = Wr1s + 16 * 64;      // 64
    float* Wr2s = br1s + 64;           // 64*256
    float* hids = Wr2s + 64 * 256;     // nwarps * EPW * 64
    int tid = threadIdx.x;
    for (int i = tid; i < 16 * 64; i += blockDim.x) Wr1s[i] = Wr1[i];
    for (int i = tid; i < 64; i += blockDim.x) br1s[i] = br1[i];
    for (int i = tid; i < 64 * 256; i += blockDim.x) Wr2s[i] = Wr2[i];
    __syncthreads();

    int warp = tid >> 5, lane = tid & 31;
    int nwarps = blockDim.x >> 5;
    float* hid = hids + warp * (EPW * 64);
    int gw = blockIdx.x * nwarps + warp;
    int wstride = gridDim.x * nwarps;
    int ntiles = NE / EPW;  // 40000, exact

    for (int tile = gw; tile < ntiles; tile += wstride) {
        int e0 = tile * EPW;
        // ---- Phase A: hidden = silu(r_feat @ Wr1 + br1) for EPW edges ----
        #pragma unroll
        for (int j = 0; j < EPW; j++) {
            int e = e0 + j;
            float rv = (lane < 16) ? g_rfeat[(size_t)e * 16 + lane] : 0.0f;
            float h0 = br1s[lane], h1 = br1s[lane + 32];
            #pragma unroll
            for (int k = 0; k < 16; k++) {
                float r = __shfl_sync(0xffffffffu, rv, k);
                h0 += r * Wr1s[k * 64 + lane];
                h1 += r * Wr1s[k * 64 + lane + 32];
            }
            h0 = h0 / (1.0f + __expf(-h0));
            h1 = h1 / (1.0f + __expf(-h1));
            hid[j * 64 + lane] = h0;
            hid[j * 64 + 32 + lane] = h1;
        }
        __syncwarp();
        // ---- Phase B: w = hidden @ Wr2, 8 edges share each B read ----
        int c0 = lane * 4;
        float4 ws[EPW], wv[EPW];
        #pragma unroll
        for (int j = 0; j < EPW; j++) {
            ws[j] = make_float4(0, 0, 0, 0);
            wv[j] = make_float4(0, 0, 0, 0);
        }
        #pragma unroll 4
        for (int h = 0; h < 64; h++) {
            float4 a = *(const float4*)(Wr2s + h * 256 + c0);
            float4 b = *(const float4*)(Wr2s + h * 256 + 128 + c0);
            #pragma unroll
            for (int j = 0; j < EPW; j++) {
                float hv = hid[j * 64 + h];  // broadcast
                ws[j] = f4fma(hv, a, ws[j]);
                wv[j] = f4fma(hv, b, wv[j]);
            }
        }
        // ---- Phase C: hoisted indices, per-edge gather + scatter ----
        int sidx[EPW], didx[EPW];
        #pragma unroll
        for (int j = 0; j < EPW; j++) {
            sidx[j] = edges[e0 + j];
            didx[j] = edges[NE + e0 + j];
        }
        #pragma unroll
        for (int j = 0; j < EPW; j++) {
            int s = sidx[j], dst = didx[j];
            if (s == dst) continue;  // mask==0
            int e = e0 + j;
            float4 hs = *(const float4*)(g_hs + (size_t)s * NC + c0);
            float4 ms = make_float4(ws[j].x * hs.x, ws[j].y * hs.y,
                                    ws[j].z * hs.z, ws[j].w * hs.w);
            red_add_v4(g_aggs + (size_t)dst * NC + c0, ms);
            float u0 = g_u[e * 3 + 0], u1 = g_u[e * 3 + 1], u2 = g_u[e * 3 + 2];
            const float* hvp = g_hv + (size_t)s * 384;
            float* avp = g_aggv + (size_t)dst * 384;
            float u3[3] = {u0, u1, u2};
            #pragma unroll
            for (int x = 0; x < 3; x++) {
                float4 hv4 = *(const float4*)(hvp + x * NC + c0);
                float u = u3[x];
                float4 mv;
                mv.x = wv[j].x * (hv4.x + hs.x * u);
                mv.y = wv[j].y * (hv4.y + hs.y * u);
                mv.z = wv[j].z * (hv4.z + hs.z * u);
                mv.w = wv[j].w * (hv4.w + hs.w * u);
                red_add_v4(avp + x * NC + c0, mv);
            }
        }
    }
}

// ---------------- 6. node s-update GEMM --------------------------------------
// s_out = a@W0 + a^2@W1 + a^3@W2 ; h_s update + feats write
// W0/W1 staged in SMEM; W2 streamed through read-only cache (fits L1/L2,
// reused by every CTA) to keep SMEM under the 227 KB sm_100a limit.
__global__ void __launch_bounds__(256) gemm_s(const float* __restrict__ Wsl, int l,
                                              float* __restrict__ outB) {
    extern __shared__ float sm[];
    float* W0 = sm;
    float* W1 = sm + 16384;
    float* As = sm + 32768;  // 64*132
    const float* W2 = Wsl + 32768;
    int tid = threadIdx.x;
    for (int i = tid; i < 2 * 16384; i += 256) sm[i] = Wsl[i];
    int m0 = blockIdx.x * 64;
    for (int i = tid; i < 64 * 32; i += 256) {
        int r = i >> 5, kq = (i & 31) * 4;
        float4 v = make_float4(0, 0, 0, 0);
        int m = m0 + r;
        if (m < NB) v = *(const float4*)(g_aggs + (size_t)m * NC + kq);
        *(float4*)(As + r * 132 + kq) = v;
    }
    __syncthreads();
    int tr = (tid >> 4) << 2;
    int tc = (tid & 15) << 3;
    float4 acc0[4] = {}, acc1[4] = {};
    for (int k = 0; k < 128; k++) {
        float4 b00 = *(const float4*)(W0 + k * 128 + tc);
        float4 b01 = *(const float4*)(W0 + k * 128 + tc + 4);
        float4 b10 = *(const float4*)(W1 + k * 128 + tc);
        float4 b11 = *(const float4*)(W1 + k * 128 + tc + 4);
        float4 b20 = __ldg((const float4*)(W2 + k * 128 + tc));
        float4 b21 = __ldg((const float4*)(W2 + k * 128 + tc + 4));
        #pragma unroll
        for (int i = 0; i < 4; i++) {
            float a = As[(tr + i) * 132 + k];
            float a2 = a * a, a3 = a2 * a;
            acc0[i] = f4fma(a, b00, acc0[i]);
            acc0[i] = f4fma(a2, b10, acc0[i]);
            acc0[i] = f4fma(a3, b20, acc0[i]);
            acc1[i] = f4fma(a, b01, acc1[i]);
            acc1[i] = f4fma(a2, b11, acc1[i]);
            acc1[i] = f4fma(a3, b21, acc1[i]);
        }
    }
    #pragma unroll
    for (int i = 0; i < 4; i++) {
        int m = m0 + tr + i;
        if (m >= NB) continue;
        float* hsrow = g_hs + (size_t)m * NC + tc;
        float4 v0 = acc0[i], v1 = acc1[i];
        if (l) {
            v0 = f4add(v0, *(float4*)hsrow);
            v1 = f4add(v1, *(float4*)(hsrow + 4));
        }
        *(float4*)hsrow = v0;
        *(float4*)(hsrow + 4) = v1;
        float* fo = outB + (size_t)m * 1024 + l * 512 + tc;
        *(float4*)fo = v0;
        *(float4*)(fo + 4) = v1;
    }
}

// ---------------- 7. node v-update GEMM --------------------------------------
// rows are (n,x): v_out = agg_v @ Wv + wsv*agg_s*agg_v ; h_v update + feats write
__global__ void __launch_bounds__(256) gemm_v(const float* __restrict__ Wvl,
                                              const float* __restrict__ wsvl, int l,
                                              float* __restrict__ outB) {
    extern __shared__ float sm[];
    float* Bs = sm;            // 128*128
    float* As = sm + 16384;    // 64*132
    __shared__ float wsvs[128];
    int tid = threadIdx.x;
    for (int i = tid; i < 16384; i += 256) Bs[i] = Wvl[i];
    if (tid < 128) wsvs[tid] = wsvl[tid];
    int m0 = blockIdx.x * 64;
    for (int i = tid; i < 64 * 32; i += 256) {
        int r = i >> 5, kq = (i & 31) * 4;
        float4 v = make_float4(0, 0, 0, 0);
        int m = m0 + r;
        if (m < NB * 3) v = *(const float4*)(g_aggv + (size_t)m * NC + kq);
        *(float4*)(As + r * 132 + kq) = v;
    }
    __syncthreads();
    int tr = (tid >> 4) << 2;
    int tc = (tid & 15) << 3;
    float4 acc0[4] = {}, acc1[4] = {};
    for (int k = 0; k < 128; k++) {
        float4 b0 = *(const float4*)(Bs + k * 128 + tc);
        float4 b1 = *(const float4*)(Bs + k * 128 + tc + 4);
        #pragma unroll
        for (int i = 0; i < 4; i++) {
            float a = As[(tr + i) * 132 + k];
            acc0[i] = f4fma(a, b0, acc0[i]);
            acc1[i] = f4fma(a, b1, acc1[i]);
        }
    }
    #pragma unroll
    for (int i = 0; i < 4; i++) {
        int m = m0 + tr + i;
        if (m >= NB * 3) continue;
        int n = m / 3;
        int x = m - 3 * n;
        float4 av0 = *(float4*)(As + (tr + i) * 132 + tc);
        float4 av1 = *(float4*)(As + (tr + i) * 132 + tc + 4);
        float4 as0 = *(const float4*)(g_aggs + (size_t)n * NC + tc);
        float4 as1 = *(const float4*)(g_aggs + (size_t)n * NC + tc + 4);
        float4 sv0 = *(const float4*)(wsvs + tc);
        float4 sv1 = *(const float4*)(wsvs + tc + 4);
        float4 r0 = acc0[i], r1 = acc1[i];
        r0.x += sv0.x * as0.x * av0.x; r0.y += sv0.y * as0.y * av0.y;
        r0.z += sv0.z * as0.z * av0.z; r0.w += sv0.w * as0.w * av0.w;
        r1.x += sv1.x * as1.x * av1.x; r1.y += sv1.y * as1.y * av1.y;
        r1.z += sv1.z * as1.z * av1.z; r1.w += sv1.w * as1.w * av1.w;
        float* hvrow = g_hv + (size_t)m * NC + tc;
        if (l) {
            r0 = f4add(r0, *(float4*)hvrow);
            r1 = f4add(r1, *(float4*)(hvrow + 4));
        }
        *(float4*)hvrow = r0;
        *(float4*)(hvrow + 4) = r1;
        // feats layout: 128 + c*3 + x
        float* fo = outB + (size_t)n * 1024 + l * 512 + 128 + x;
        fo[(tc + 0) * 3] = r0.x; fo[(tc + 1) * 3] = r0.y;
        fo[(tc + 2) * 3] = r0.z; fo[(tc + 3) * 3] = r0.w;
        fo[(tc + 4) * 3] = r1.x; fo[(tc + 5) * 3] = r1.y;
        fo[(tc + 6) * 3] = r1.z; fo[(tc + 7) * 3] = r1.w;
    }
}

// ---------------- 8. normalize rows + scatter to graphs ----------------------
__global__ void norm_block(float* __restrict__ outB, float* __restrict__ outC,
                           const int* __restrict__ batch_id) {
    int t = blockIdx.x * blockDim.x + threadIdx.x;
    int n = t >> 5;
    if (n >= NB) return;
    int lane = t & 31;
    float* row = outB + (size_t)n * 1024;
    float4 v[8];
    float ss = 0.0f;
    #pragma unroll
    for (int i = 0; i < 8; i++) {
        v[i] = *(float4*)(row + i * 128 + lane * 4);
        ss += v[i].x * v[i].x + v[i].y * v[i].y + v[i].z * v[i].z + v[i].w * v[i].w;
    }
    #pragma unroll
    for (int o = 16; o; o >>= 1) ss += __shfl_xor_sync(0xffffffffu, ss, o);
    float inv = 1.0f / fmaxf(sqrtf(ss), 1e-12f);
    int b = batch_id[n];
    float* grow = outC + (size_t)b * 1024;
    #pragma unroll
    for (int i = 0; i < 8; i++) {
        v[i] = f4scale(v[i], inv);
        *(float4*)(row + i * 128 + lane * 4) = v[i];
        red_add_v4(grow + i * 128 + lane * 4, v[i]);
    }
}

__global__ void norm_g(float* __restrict__ outC) {
    int t = blockIdx.x * blockDim.x + threadIdx.x;
    int n = t >> 5;
    if (n >= NG) return;
    int lane = t & 31;
    float* row = outC + (size_t)n * 1024;
    float4 v[8];
    float ss = 0.0f;
    #pragma unroll
    for (int i = 0; i < 8; i++) {
        v[i] = *(float4*)(row + i * 128 + lane * 4);
        ss += v[i].x * v[i].x + v[i].y * v[i].y + v[i].z * v[i].z + v[i].w * v[i].w;
    }
    #pragma unroll
    for (int o = 16; o; o >>= 1) ss += __shfl_xor_sync(0xffffffffu, ss, o);
    float inv = 1.0f / fmaxf(sqrtf(ss), 1e-12f);
    #pragma unroll
    for (int i = 0; i < 8; i++)
        *(float4*)(row + i * 128 + lane * 4) = f4scale(v[i], inv);
}

// ---------------- launch ------------------------------------------------------
extern "C" void kernel_launch(void* const* d_in, const int* in_sizes, int n_in,
                              void* d_out, int out_size) {
    const float* H       = (const float*)d_in[0];
    const float* Z       = (const float*)d_in[1];
    const float* W_embed = (const float*)d_in[2];
    const float* Wr1     = (const float*)d_in[3];
    const float* br1     = (const float*)d_in[4];
    const float* Wr2     = (const float*)d_in[5];
    const float* Ws      = (const float*)d_in[6];
    const float* Wv      = (const float*)d_in[7];
    const float* wsv     = (const float*)d_in[8];
    const int* block_id  = (const int*)d_in[9];
    const int* batch_id  = (const int*)d_in[10];
    const int* edges     = (const int*)d_in[11];

    float* outA = (float*)d_out;                    // Hb        [20000,128]
    float* outB = outA + (size_t)NB * NC;           // block_repr[20000,1024]
    float* outC = outB + (size_t)NB * 1024;         // graph_repr[512,1024]

    const int EM_SMEM = (16 * 64 + 64 + 64 * 256 + 8 * EPW * 64) * 4;  // ~86 KB
    const int GS_SMEM = (2 * 16384 + 64 * 132) * 4;                 // 164864
    const int GV_SMEM = (16384 + 64 * 132) * 4;                     // 99328

    cudaFuncSetAttribute(edge_msg,   cudaFuncAttributeMaxDynamicSharedMemorySize, EM_SMEM);
    cudaFuncSetAttribute(gemm_s,     cudaFuncAttributeMaxDynamicSharedMemorySize, GS_SMEM);
    cudaFuncSetAttribute(gemm_v,     cudaFuncAttributeMaxDynamicSharedMemorySize, GV_SMEM);
    cudaFuncSetAttribute(gemm_embed, cudaFuncAttributeMaxDynamicSharedMemorySize, GV_SMEM);

    void *pZb, *pcnt, *phv, *paggs, *paggv;
    cudaGetSymbolAddress(&pZb, g_Zb);
    cudaGetSymbolAddress(&pcnt, g_cnt);
    cudaGetSymbolAddress(&phv, g_hv);
    cudaGetSymbolAddress(&paggs, g_aggs);
    cudaGetSymbolAddress(&paggv, g_aggv);

    cudaMemsetAsync(outA, 0, (size_t)NB * NC * 4);
    cudaMemsetAsync(outC, 0, (size_t)NG * 1024 * 4);
    cudaMemsetAsync(pZb, 0, (size_t)NB * 3 * 4);
    cudaMemsetAsync(pcnt, 0, (size_t)NB * 4);
    cudaMemsetAsync(phv, 0, (size_t)NB * 384 * 4);

    atom_scatter<<<(NA * 32 + 255) / 256, 256>>>(H, Z, block_id, outA);
    finalize_blocks<<<(NB * 32 + 255) / 256, 256>>>(outA);
    gemm_embed<<<(NB + 63) / 64, 256, GV_SMEM>>>(outA, W_embed);
    edge_geom<<<(NE + 255) / 256, 256>>>(edges);

    for (int l = 0; l < 2; l++) {
        cudaMemsetAsync(paggs, 0, (size_t)NB * NC * 4);
        cudaMemsetAsync(paggv, 0, (size_t)NB * 384 * 4);
        edge_msg<<<296, 256, EM_SMEM>>>(edges, Wr1 + l * 16 * 64, br1 + l * 64,
                                        Wr2 + l * 64 * 256);
        gemm_s<<<(NB + 63) / 64, 256, GS_SMEM>>>(Ws + (size_t)l * 3 * 16384, l, outB);
        gemm_v<<<(NB * 3 + 63) / 64, 256, GV_SMEM>>>(Wv + (size_t)l * 16384,
                                                     wsv + l * 128, l, outB);
    }

    norm_block<<<(NB * 32 + 255) / 256, 256>>>(outB, outC, batch_id);
    norm_g<<<(NG * 32 + 255) / 256, 256>>>(outC);
}